// round 5
// baseline (speedup 1.0000x reference)
#include <cuda_runtime.h>
#include <math.h>

// ---------------------------------------------------------------------------
// CellularAutomatonDecoder — fused, ONE batch row per CTA (R5: occupancy).
// B=2048, T=32, D=128, V=256, H=256, 8 evolution steps. fp32 FFMA2 everywhere.
// smem/CTA = 50,176B -> 3 CTAs/SM (24 warps), launch_bounds(256,3) caps 85 regs.
// ---------------------------------------------------------------------------

typedef unsigned long long ull;

__device__ float g_cb[256];   // const_bias = rule_bias @ W1b + b1
__device__ float g_asig;      // sigmoid(alpha)

__device__ __forceinline__ ull dup2(float x) {
    ull r; asm("mov.b64 %0, {%1, %1};" : "=l"(r) : "f"(x)); return r;
}
__device__ __forceinline__ ull pack2(float lo, float hi) {
    ull r; asm("mov.b64 %0, {%1, %2};" : "=l"(r) : "f"(lo), "f"(hi)); return r;
}
__device__ __forceinline__ float2 unpack2(ull v) {
    float lo, hi; asm("mov.b64 {%0, %1}, %2;" : "=f"(lo), "=f"(hi) : "l"(v));
    return make_float2(lo, hi);
}
__device__ __forceinline__ void ffma2(ull& d, ull a, ull b) {
    asm("fma.rn.f32x2 %0, %1, %2, %0;" : "+l"(d) : "l"(a), "l"(b));
}

// exact (non-approximate) GELU, matches jax.nn.gelu(approximate=False)
__device__ __forceinline__ float gelu_exact(float x) {
    return 0.5f * x * (1.0f + erff(x * 0.70710678118654752440f));
}
// accurate tanh; expm1 form is small-x safe and immune to fast-math rewrites
__device__ __forceinline__ float tanh_acc(float x) {
    float ax  = fabsf(x);
    float em1 = expm1f(-2.0f * ax);
    float r   = -em1 / (em1 + 2.0f);
    return copysignf(r, x);
}

// ---------------------------------------------------------------------------
// Preamble (1 block): c_pooled -> rule_bias -> const_bias, sigmoid(alpha)
// ---------------------------------------------------------------------------
__global__ void ca_preamble(const float* __restrict__ c_states,
                            const float* __restrict__ W1,
                            const float* __restrict__ b1,
                            const float* __restrict__ Wc1,
                            const float* __restrict__ bc1,
                            const float* __restrict__ Wc2,
                            const float* __restrict__ bc2,
                            const float* __restrict__ alpha) {
    __shared__ float cp[128];
    __shared__ float h1[256];
    __shared__ float rb[128];
    const int tid = threadIdx.x;

    if (tid < 128)
        cp[tid] = 0.25f * (c_states[tid] + c_states[128 + tid] +
                           c_states[256 + tid] + c_states[384 + tid]);
    __syncthreads();
    {
        float s = bc1[tid];
        for (int k = 0; k < 128; ++k) s = fmaf(cp[k], Wc1[k * 256 + tid], s);
        h1[tid] = gelu_exact(s);
    }
    __syncthreads();
    if (tid < 128) {
        float r = bc2[tid];
        for (int j = 0; j < 256; ++j) r = fmaf(h1[j], Wc2[j * 128 + tid], r);
        rb[tid] = r;
    }
    __syncthreads();
    {
        float s = b1[tid];
        for (int d = 0; d < 128; ++d)
            s = fmaf(rb[d], W1[(384 + d) * 256 + tid], s);
        g_cb[tid] = s;
    }
    if (tid == 0) g_asig = 1.0f / (1.0f + expf(-alpha[0]));
}

// ---------------------------------------------------------------------------
// Main fused kernel. CTA = 256 threads = 8 warps, ONE batch row. grid = 2048.
// SMEM: cells padded [34][128] (ghost rows 0,33) at 0; hidden [32][256] at 4352.
//   total = 12544 floats = 50176 B -> 3 CTAs/SM.
// Warp mapping:
//   GEMM1/head: cg = wid&1 (128-col group), th = wid>>1 (8-row quarter)
//               thread = 8 t-rows x 4 cols (j0 = cg*128 + lane*4)
//   GEMM2/LN:   thread = 4 t-rows x 4 dims (t02 = wid*4, d0 = lane*4)
// ---------------------------------------------------------------------------
__global__ void __launch_bounds__(256, 3)
ca_main(const int*   __restrict__ tokens,
        const float* __restrict__ embed,
        const float* __restrict__ pos_embed,
        const float* __restrict__ W1,
        const float* __restrict__ W2,
        const float* __restrict__ b2,
        const float* __restrict__ ln_g,
        const float* __restrict__ ln_b,
        const float* __restrict__ head_w,
        float* __restrict__ out) {
    extern __shared__ float smem[];
    float* scr = smem;          // [34][128] padded cells
    float* shr = smem + 4352;   // [32][256] hidden

    const int tid  = threadIdx.x;
    const int wid  = tid >> 5;
    const int lane = tid & 31;

    const int cg  = wid & 1;
    const int th  = wid >> 1;
    const int t0g = th * 8;
    const int j0  = cg * 128 + lane * 4;
    const int t02 = wid * 4;
    const int d0  = lane * 4;

    const int b = blockIdx.x;

    // ---- init cells: embed[tokens] + pos_embed (padded rows 1..32)
    for (int idx = tid; idx < 4096; idx += 256) {
        int t = idx >> 7, d = idx & 127;
        scr[(t + 1) * 128 + d] =
            embed[tokens[b * 32 + t] * 128 + d] + pos_embed[idx];
    }
    __syncthreads();
    if (tid < 256) {   // ghost rows (256 threads cover 2x128)
        int g = tid >> 7, d = tid & 127;
        if (g) scr[33 * 128 + d] = scr[1 * 128 + d];     // row33 = t0
        else   scr[d]            = scr[32 * 128 + d];    // row0  = t31
    }
    __syncthreads();

    const float aev = g_asig;
    const float bev = 1.0f - aev;
    const ull cb0 = pack2(g_cb[j0],     g_cb[j0 + 1]);
    const ull cb1 = pack2(g_cb[j0 + 2], g_cb[j0 + 3]);
    const ull bb0 = pack2(b2[d0],     b2[d0 + 1]);
    const ull bb1 = pack2(b2[d0 + 2], b2[d0 + 3]);

    // =============== 8 evolution steps ===============
    for (int step = 0; step < 8; ++step) {
        // ---- GEMM1: pre = c@W1c + left@W1l + right@W1r + cb; sh = gelu(pre)
        ull acc[8][2];
#pragma unroll
        for (int t = 0; t < 8; ++t) { acc[t][0] = cb0; acc[t][1] = cb1; }
        {
            const float* wp = W1 + j0;
            const float* ap = scr + t0g * 128;
#pragma unroll 1
            for (int k2 = 0; k2 < 64; ++k2) {
                ulonglong2 wcA = *(const ulonglong2*)(wp);
                ulonglong2 wcB = *(const ulonglong2*)(wp + 256);
                ulonglong2 wlA = *(const ulonglong2*)(wp + 32768);
                ulonglong2 wlB = *(const ulonglong2*)(wp + 33024);
                ulonglong2 wrA = *(const ulonglong2*)(wp + 65536);
                ulonglong2 wrB = *(const ulonglong2*)(wp + 65792);
                float2 aP = *(const float2*)(ap);         // row t0-1 (padded)
                float2 aC = *(const float2*)(ap + 128);   // row t0
                ull dPx = dup2(aP.x), dPy = dup2(aP.y);
                ull dCx = dup2(aC.x), dCy = dup2(aC.y);
#pragma unroll
                for (int t = 0; t < 8; ++t) {
                    float2 aN = *(const float2*)(ap + (t + 2) * 128);
                    ull dNx = dup2(aN.x), dNy = dup2(aN.y);
                    ffma2(acc[t][0], dCx, wcA.x); ffma2(acc[t][1], dCx, wcA.y);
                    ffma2(acc[t][0], dPx, wlA.x); ffma2(acc[t][1], dPx, wlA.y);
                    ffma2(acc[t][0], dNx, wrA.x); ffma2(acc[t][1], dNx, wrA.y);
                    ffma2(acc[t][0], dCy, wcB.x); ffma2(acc[t][1], dCy, wcB.y);
                    ffma2(acc[t][0], dPy, wlB.x); ffma2(acc[t][1], dPy, wlB.y);
                    ffma2(acc[t][0], dNy, wrB.x); ffma2(acc[t][1], dNy, wrB.y);
                    dPx = dCx; dPy = dCy; dCx = dNx; dCy = dNy;
                }
                wp += 512;
                ap += 2;
            }
        }
#pragma unroll
        for (int t = 0; t < 8; ++t) {
            float2 v0 = unpack2(acc[t][0]);
            float2 v1 = unpack2(acc[t][1]);
            *(float4*)(shr + (t0g + t) * 256 + j0) =
                make_float4(gelu_exact(v0.x), gelu_exact(v0.y),
                            gelu_exact(v1.x), gelu_exact(v1.y));
        }
        __syncthreads();

        // ---- GEMM2: new = tanh(hidden @ W2 + b2); EMA blend into cells
        ull a2[4][2];
#pragma unroll
        for (int t = 0; t < 4; ++t) { a2[t][0] = bb0; a2[t][1] = bb1; }
        {
            const float* w2p = W2 + d0;
            const float* hp  = shr + t02 * 256;
#pragma unroll 1
            for (int k2 = 0; k2 < 128; ++k2) {
                ulonglong2 wA = *(const ulonglong2*)(w2p);
                ulonglong2 wB = *(const ulonglong2*)(w2p + 128);
#pragma unroll
                for (int t = 0; t < 4; ++t) {
                    float2 h = *(const float2*)(hp + t * 256);
                    ull hx = dup2(h.x), hy = dup2(h.y);
                    ffma2(a2[t][0], hx, wA.x); ffma2(a2[t][1], hx, wA.y);
                    ffma2(a2[t][0], hy, wB.x); ffma2(a2[t][1], hy, wB.y);
                }
                w2p += 256;
                hp  += 2;
            }
        }
#pragma unroll
        for (int t = 0; t < 4; ++t) {
            float* cp = scr + (t02 + t + 1) * 128 + d0;
            float4 o = *(float4*)cp;            // own cells only: no hazard
            float2 v0 = unpack2(a2[t][0]);
            float2 v1 = unpack2(a2[t][1]);
            float4 n;
            n.x = aev * o.x + bev * tanh_acc(v0.x);
            n.y = aev * o.y + bev * tanh_acc(v0.y);
            n.z = aev * o.z + bev * tanh_acc(v1.x);
            n.w = aev * o.w + bev * tanh_acc(v1.y);
            *(float4*)cp = n;
            int tg = t02 + t;
            if (tg == 0)  *(float4*)(scr + 33 * 128 + d0) = n;  // ghost top
            if (tg == 31) *(float4*)(scr + d0)            = n;  // ghost bottom
        }
        __syncthreads();
    }

    // ---- LayerNorm in place (padded rows 1..32); warp = 4 rows
    {
        float g0 = ln_g[lane],      g1 = ln_g[lane + 32];
        float g2 = ln_g[lane + 64], g3 = ln_g[lane + 96];
        float e0 = ln_b[lane],      e1 = ln_b[lane + 32];
        float e2 = ln_b[lane + 64], e3 = ln_b[lane + 96];
#pragma unroll
        for (int t = 0; t < 4; ++t) {
            float* p = scr + (t02 + t + 1) * 128;
            float x0 = p[lane], x1 = p[lane + 32];
            float x2 = p[lane + 64], x3 = p[lane + 96];
            float sm = x0 + x1 + x2 + x3;
            float sq = x0 * x0 + x1 * x1 + x2 * x2 + x3 * x3;
#pragma unroll
            for (int off = 16; off > 0; off >>= 1) {
                sm += __shfl_xor_sync(0xffffffffu, sm, off);
                sq += __shfl_xor_sync(0xffffffffu, sq, off);
            }
            float mu  = sm * (1.0f / 128.0f);
            float var = sq * (1.0f / 128.0f) - mu * mu;
            float rs  = rsqrtf(var + 1e-5f);
            p[lane]      = (x0 - mu) * rs * g0 + e0;
            p[lane + 32] = (x1 - mu) * rs * g1 + e1;
            p[lane + 64] = (x2 - mu) * rs * g2 + e2;
            p[lane + 96] = (x3 - mu) * rs * g3 + e3;
        }
    }
    __syncthreads();

    // ---- Head: logits = cellsN @ head_w  (32 x 256)
    {
        ull ha[8][2];
#pragma unroll
        for (int t = 0; t < 8; ++t) { ha[t][0] = 0ULL; ha[t][1] = 0ULL; }
        const float* hwp = head_w + j0;
        const float* ap  = scr + (t0g + 1) * 128;
#pragma unroll 1
        for (int k2 = 0; k2 < 64; ++k2) {
            ulonglong2 wA = *(const ulonglong2*)(hwp);
            ulonglong2 wB = *(const ulonglong2*)(hwp + 256);
#pragma unroll
            for (int t = 0; t < 8; ++t) {
                float2 x = *(const float2*)(ap + t * 128);
                ull xx = dup2(x.x), xy = dup2(x.y);
                ffma2(ha[t][0], xx, wA.x); ffma2(ha[t][1], xx, wA.y);
                ffma2(ha[t][0], xy, wB.x); ffma2(ha[t][1], xy, wB.y);
            }
            hwp += 512;
            ap  += 2;
        }
        float* ob = out + ((size_t)b * 32 + t0g) * 256 + j0;
#pragma unroll
        for (int t = 0; t < 8; ++t) {
            float2 p0 = unpack2(ha[t][0]);
            float2 p1 = unpack2(ha[t][1]);
            *(float4*)(ob + (size_t)t * 256) =
                make_float4(p0.x, p0.y, p1.x, p1.y);
        }
    }
}

// ---------------------------------------------------------------------------
extern "C" void kernel_launch(void* const* d_in, const int* in_sizes, int n_in,
                              void* d_out, int out_size) {
    const int*   tokens    = (const int*)  d_in[0];
    const float* c_states  = (const float*)d_in[1];
    const float* embed     = (const float*)d_in[2];
    const float* pos_embed = (const float*)d_in[3];
    const float* W1        = (const float*)d_in[4];
    const float* b1        = (const float*)d_in[5];
    const float* W2        = (const float*)d_in[6];
    const float* b2        = (const float*)d_in[7];
    const float* Wc1       = (const float*)d_in[8];
    const float* bc1       = (const float*)d_in[9];
    const float* Wc2       = (const float*)d_in[10];
    const float* bc2       = (const float*)d_in[11];
    const float* alpha     = (const float*)d_in[12];
    const float* ln_g      = (const float*)d_in[13];
    const float* ln_b      = (const float*)d_in[14];
    const float* head_w    = (const float*)d_in[15];
    float* out = (float*)d_out;

    cudaFuncSetAttribute(ca_main, cudaFuncAttributeMaxDynamicSharedMemorySize,
                         50176);
    ca_preamble<<<1, 256>>>(c_states, W1, b1, Wc1, bc1, Wc2, bc2, alpha);
    ca_main<<<2048, 256, 50176>>>(tokens, embed, pos_embed, W1, W2, b2,
                                  ln_g, ln_b, head_w, out);
}

// round 7
// speedup vs baseline: 1.0018x; 1.0018x over previous
#include <cuda_runtime.h>
#include <math.h>

// ---------------------------------------------------------------------------
// CellularAutomatonDecoder — fused, ONE batch row per CTA (R5: occupancy).
// B=2048, T=32, D=128, V=256, H=256, 8 evolution steps. fp32 FFMA2 everywhere.
// smem/CTA = 50,176B -> 3 CTAs/SM (24 warps), launch_bounds(256,3) caps 85 regs.
// ---------------------------------------------------------------------------

typedef unsigned long long ull;

__device__ float g_cb[256];   // const_bias = rule_bias @ W1b + b1
__device__ float g_asig;      // sigmoid(alpha)

__device__ __forceinline__ ull dup2(float x) {
    ull r; asm("mov.b64 %0, {%1, %1};" : "=l"(r) : "f"(x)); return r;
}
__device__ __forceinline__ ull pack2(float lo, float hi) {
    ull r; asm("mov.b64 %0, {%1, %2};" : "=l"(r) : "f"(lo), "f"(hi)); return r;
}
__device__ __forceinline__ float2 unpack2(ull v) {
    float lo, hi; asm("mov.b64 {%0, %1}, %2;" : "=f"(lo), "=f"(hi) : "l"(v));
    return make_float2(lo, hi);
}
__device__ __forceinline__ void ffma2(ull& d, ull a, ull b) {
    asm("fma.rn.f32x2 %0, %1, %2, %0;" : "+l"(d) : "l"(a), "l"(b));
}

// exact (non-approximate) GELU, matches jax.nn.gelu(approximate=False)
__device__ __forceinline__ float gelu_exact(float x) {
    return 0.5f * x * (1.0f + erff(x * 0.70710678118654752440f));
}
// accurate tanh; expm1 form is small-x safe and immune to fast-math rewrites
__device__ __forceinline__ float tanh_acc(float x) {
    float ax  = fabsf(x);
    float em1 = expm1f(-2.0f * ax);
    float r   = -em1 / (em1 + 2.0f);
    return copysignf(r, x);
}

// ---------------------------------------------------------------------------
// Preamble (1 block): c_pooled -> rule_bias -> const_bias, sigmoid(alpha)
// ---------------------------------------------------------------------------
__global__ void ca_preamble(const float* __restrict__ c_states,
                            const float* __restrict__ W1,
                            const float* __restrict__ b1,
                            const float* __restrict__ Wc1,
                            const float* __restrict__ bc1,
                            const float* __restrict__ Wc2,
                            const float* __restrict__ bc2,
                            const float* __restrict__ alpha) {
    __shared__ float cp[128];
    __shared__ float h1[256];
    __shared__ float rb[128];
    const int tid = threadIdx.x;

    if (tid < 128)
        cp[tid] = 0.25f * (c_states[tid] + c_states[128 + tid] +
                           c_states[256 + tid] + c_states[384 + tid]);
    __syncthreads();
    {
        float s = bc1[tid];
        for (int k = 0; k < 128; ++k) s = fmaf(cp[k], Wc1[k * 256 + tid], s);
        h1[tid] = gelu_exact(s);
    }
    __syncthreads();
    if (tid < 128) {
        float r = bc2[tid];
        for (int j = 0; j < 256; ++j) r = fmaf(h1[j], Wc2[j * 128 + tid], r);
        rb[tid] = r;
    }
    __syncthreads();
    {
        float s = b1[tid];
        for (int d = 0; d < 128; ++d)
            s = fmaf(rb[d], W1[(384 + d) * 256 + tid], s);
        g_cb[tid] = s;
    }
    if (tid == 0) g_asig = 1.0f / (1.0f + expf(-alpha[0]));
}

// ---------------------------------------------------------------------------
// Main fused kernel. CTA = 256 threads = 8 warps, ONE batch row. grid = 2048.
// SMEM: cells padded [34][128] (ghost rows 0,33) at 0; hidden [32][256] at 4352.
//   total = 12544 floats = 50176 B -> 3 CTAs/SM.
// Warp mapping:
//   GEMM1/head: cg = wid&1 (128-col group), th = wid>>1 (8-row quarter)
//               thread = 8 t-rows x 4 cols (j0 = cg*128 + lane*4)
//   GEMM2/LN:   thread = 4 t-rows x 4 dims (t02 = wid*4, d0 = lane*4)
// ---------------------------------------------------------------------------
__global__ void __launch_bounds__(256, 3)
ca_main(const int*   __restrict__ tokens,
        const float* __restrict__ embed,
        const float* __restrict__ pos_embed,
        const float* __restrict__ W1,
        const float* __restrict__ W2,
        const float* __restrict__ b2,
        const float* __restrict__ ln_g,
        const float* __restrict__ ln_b,
        const float* __restrict__ head_w,
        float* __restrict__ out) {
    extern __shared__ float smem[];
    float* scr = smem;          // [34][128] padded cells
    float* shr = smem + 4352;   // [32][256] hidden

    const int tid  = threadIdx.x;
    const int wid  = tid >> 5;
    const int lane = tid & 31;

    const int cg  = wid & 1;
    const int th  = wid >> 1;
    const int t0g = th * 8;
    const int j0  = cg * 128 + lane * 4;
    const int t02 = wid * 4;
    const int d0  = lane * 4;

    const int b = blockIdx.x;

    // ---- init cells: embed[tokens] + pos_embed (padded rows 1..32)
    for (int idx = tid; idx < 4096; idx += 256) {
        int t = idx >> 7, d = idx & 127;
        scr[(t + 1) * 128 + d] =
            embed[tokens[b * 32 + t] * 128 + d] + pos_embed[idx];
    }
    __syncthreads();
    if (tid < 256) {   // ghost rows (256 threads cover 2x128)
        int g = tid >> 7, d = tid & 127;
        if (g) scr[33 * 128 + d] = scr[1 * 128 + d];     // row33 = t0
        else   scr[d]            = scr[32 * 128 + d];    // row0  = t31
    }
    __syncthreads();

    const float aev = g_asig;
    const float bev = 1.0f - aev;
    const ull cb0 = pack2(g_cb[j0],     g_cb[j0 + 1]);
    const ull cb1 = pack2(g_cb[j0 + 2], g_cb[j0 + 3]);
    const ull bb0 = pack2(b2[d0],     b2[d0 + 1]);
    const ull bb1 = pack2(b2[d0 + 2], b2[d0 + 3]);

    // =============== 8 evolution steps ===============
    for (int step = 0; step < 8; ++step) {
        // ---- GEMM1: pre = c@W1c + left@W1l + right@W1r + cb; sh = gelu(pre)
        ull acc[8][2];
#pragma unroll
        for (int t = 0; t < 8; ++t) { acc[t][0] = cb0; acc[t][1] = cb1; }
        {
            const float* wp = W1 + j0;
            const float* ap = scr + t0g * 128;
#pragma unroll 1
            for (int k2 = 0; k2 < 64; ++k2) {
                ulonglong2 wcA = *(const ulonglong2*)(wp);
                ulonglong2 wcB = *(const ulonglong2*)(wp + 256);
                ulonglong2 wlA = *(const ulonglong2*)(wp + 32768);
                ulonglong2 wlB = *(const ulonglong2*)(wp + 33024);
                ulonglong2 wrA = *(const ulonglong2*)(wp + 65536);
                ulonglong2 wrB = *(const ulonglong2*)(wp + 65792);
                float2 aP = *(const float2*)(ap);         // row t0-1 (padded)
                float2 aC = *(const float2*)(ap + 128);   // row t0
                ull dPx = dup2(aP.x), dPy = dup2(aP.y);
                ull dCx = dup2(aC.x), dCy = dup2(aC.y);
#pragma unroll
                for (int t = 0; t < 8; ++t) {
                    float2 aN = *(const float2*)(ap + (t + 2) * 128);
                    ull dNx = dup2(aN.x), dNy = dup2(aN.y);
                    ffma2(acc[t][0], dCx, wcA.x); ffma2(acc[t][1], dCx, wcA.y);
                    ffma2(acc[t][0], dPx, wlA.x); ffma2(acc[t][1], dPx, wlA.y);
                    ffma2(acc[t][0], dNx, wrA.x); ffma2(acc[t][1], dNx, wrA.y);
                    ffma2(acc[t][0], dCy, wcB.x); ffma2(acc[t][1], dCy, wcB.y);
                    ffma2(acc[t][0], dPy, wlB.x); ffma2(acc[t][1], dPy, wlB.y);
                    ffma2(acc[t][0], dNy, wrB.x); ffma2(acc[t][1], dNy, wrB.y);
                    dPx = dCx; dPy = dCy; dCx = dNx; dCy = dNy;
                }
                wp += 512;
                ap += 2;
            }
        }
#pragma unroll
        for (int t = 0; t < 8; ++t) {
            float2 v0 = unpack2(acc[t][0]);
            float2 v1 = unpack2(acc[t][1]);
            *(float4*)(shr + (t0g + t) * 256 + j0) =
                make_float4(gelu_exact(v0.x), gelu_exact(v0.y),
                            gelu_exact(v1.x), gelu_exact(v1.y));
        }
        __syncthreads();

        // ---- GEMM2: new = tanh(hidden @ W2 + b2); EMA blend into cells
        ull a2[4][2];
#pragma unroll
        for (int t = 0; t < 4; ++t) { a2[t][0] = bb0; a2[t][1] = bb1; }
        {
            const float* w2p = W2 + d0;
            const float* hp  = shr + t02 * 256;
#pragma unroll 1
            for (int k2 = 0; k2 < 128; ++k2) {
                ulonglong2 wA = *(const ulonglong2*)(w2p);
                ulonglong2 wB = *(const ulonglong2*)(w2p + 128);
#pragma unroll
                for (int t = 0; t < 4; ++t) {
                    float2 h = *(const float2*)(hp + t * 256);
                    ull hx = dup2(h.x), hy = dup2(h.y);
                    ffma2(a2[t][0], hx, wA.x); ffma2(a2[t][1], hx, wA.y);
                    ffma2(a2[t][0], hy, wB.x); ffma2(a2[t][1], hy, wB.y);
                }
                w2p += 256;
                hp  += 2;
            }
        }
#pragma unroll
        for (int t = 0; t < 4; ++t) {
            float* cp = scr + (t02 + t + 1) * 128 + d0;
            float4 o = *(float4*)cp;            // own cells only: no hazard
            float2 v0 = unpack2(a2[t][0]);
            float2 v1 = unpack2(a2[t][1]);
            float4 n;
            n.x = aev * o.x + bev * tanh_acc(v0.x);
            n.y = aev * o.y + bev * tanh_acc(v0.y);
            n.z = aev * o.z + bev * tanh_acc(v1.x);
            n.w = aev * o.w + bev * tanh_acc(v1.y);
            *(float4*)cp = n;
            int tg = t02 + t;
            if (tg == 0)  *(float4*)(scr + 33 * 128 + d0) = n;  // ghost top
            if (tg == 31) *(float4*)(scr + d0)            = n;  // ghost bottom
        }
        __syncthreads();
    }

    // ---- LayerNorm in place (padded rows 1..32); warp = 4 rows
    {
        float g0 = ln_g[lane],      g1 = ln_g[lane + 32];
        float g2 = ln_g[lane + 64], g3 = ln_g[lane + 96];
        float e0 = ln_b[lane],      e1 = ln_b[lane + 32];
        float e2 = ln_b[lane + 64], e3 = ln_b[lane + 96];
#pragma unroll
        for (int t = 0; t < 4; ++t) {
            float* p = scr + (t02 + t + 1) * 128;
            float x0 = p[lane], x1 = p[lane + 32];
            float x2 = p[lane + 64], x3 = p[lane + 96];
            float sm = x0 + x1 + x2 + x3;
            float sq = x0 * x0 + x1 * x1 + x2 * x2 + x3 * x3;
#pragma unroll
            for (int off = 16; off > 0; off >>= 1) {
                sm += __shfl_xor_sync(0xffffffffu, sm, off);
                sq += __shfl_xor_sync(0xffffffffu, sq, off);
            }
            float mu  = sm * (1.0f / 128.0f);
            float var = sq * (1.0f / 128.0f) - mu * mu;
            float rs  = rsqrtf(var + 1e-5f);
            p[lane]      = (x0 - mu) * rs * g0 + e0;
            p[lane + 32] = (x1 - mu) * rs * g1 + e1;
            p[lane + 64] = (x2 - mu) * rs * g2 + e2;
            p[lane + 96] = (x3 - mu) * rs * g3 + e3;
        }
    }
    __syncthreads();

    // ---- Head: logits = cellsN @ head_w  (32 x 256)
    {
        ull ha[8][2];
#pragma unroll
        for (int t = 0; t < 8; ++t) { ha[t][0] = 0ULL; ha[t][1] = 0ULL; }
        const float* hwp = head_w + j0;
        const float* ap  = scr + (t0g + 1) * 128;
#pragma unroll 1
        for (int k2 = 0; k2 < 64; ++k2) {
            ulonglong2 wA = *(const ulonglong2*)(hwp);
            ulonglong2 wB = *(const ulonglong2*)(hwp + 256);
#pragma unroll
            for (int t = 0; t < 8; ++t) {
                float2 x = *(const float2*)(ap + t * 128);
                ull xx = dup2(x.x), xy = dup2(x.y);
                ffma2(ha[t][0], xx, wA.x); ffma2(ha[t][1], xx, wA.y);
                ffma2(ha[t][0], xy, wB.x); ffma2(ha[t][1], xy, wB.y);
            }
            hwp += 512;
            ap  += 2;
        }
        float* ob = out + ((size_t)b * 32 + t0g) * 256 + j0;
#pragma unroll
        for (int t = 0; t < 8; ++t) {
            float2 p0 = unpack2(ha[t][0]);
            float2 p1 = unpack2(ha[t][1]);
            *(float4*)(ob + (size_t)t * 256) =
                make_float4(p0.x, p0.y, p1.x, p1.y);
        }
    }
}

// ---------------------------------------------------------------------------
extern "C" void kernel_launch(void* const* d_in, const int* in_sizes, int n_in,
                              void* d_out, int out_size) {
    const int*   tokens    = (const int*)  d_in[0];
    const float* c_states  = (const float*)d_in[1];
    const float* embed     = (const float*)d_in[2];
    const float* pos_embed = (const float*)d_in[3];
    const float* W1        = (const float*)d_in[4];
    const float* b1        = (const float*)d_in[5];
    const float* W2        = (const float*)d_in[6];
    const float* b2        = (const float*)d_in[7];
    const float* Wc1       = (const float*)d_in[8];
    const float* bc1       = (const float*)d_in[9];
    const float* Wc2       = (const float*)d_in[10];
    const float* bc2       = (const float*)d_in[11];
    const float* alpha     = (const float*)d_in[12];
    const float* ln_g      = (const float*)d_in[13];
    const float* ln_b      = (const float*)d_in[14];
    const float* head_w    = (const float*)d_in[15];
    float* out = (float*)d_out;

    cudaFuncSetAttribute(ca_main, cudaFuncAttributeMaxDynamicSharedMemorySize,
                         50176);
    ca_preamble<<<1, 256>>>(c_states, W1, b1, Wc1, bc1, Wc2, bc2, alpha);
    ca_main<<<2048, 256, 50176>>>(tokens, embed, pos_embed, W1, W2, b2,
                                  ln_g, ln_b, head_w, out);
}